// round 2
// baseline (speedup 1.0000x reference)
#include <cuda_runtime.h>
#include <cuda_bf16.h>
#include <math_constants.h>

// ---------------------------------------------------------------------------
// GAT 2-layer + softmax head.
//   layer: h = x@W ; as = h@a_src ; ad = h@a_dst
//          per edge (src,dst) incl self-loops: e = exp(leakyrelu(as[s]+ad[d]))
//          z[d] += e ; acc[d] += e * h[s]
//          next-layer input = relu(acc/z + b)
// Max-shift in segment-softmax is skipped (shift-invariant; logits are O(1)).
// Division by z deferred to the following node kernel.
// ---------------------------------------------------------------------------

#define NMAX 100000
#define IN_DIM 512
#define HID 16

// persistent scratch (no allocation allowed)
__device__ __align__(16) float g_h[NMAX * HID];     // node features of current layer
__device__ __align__(16) float g_acc[NMAX * HID];   // edge-aggregated numerator
__device__ float g_as[NMAX];
__device__ float g_ad[NMAX];
__device__ float g_z[NMAX];

// ---------------------------------------------------------------------------
// vec4 global reduction (sm_90+)
__device__ __forceinline__ void redAdd4(float* p, float a, float b, float c, float d) {
    asm volatile("red.global.add.v4.f32 [%0], {%1,%2,%3,%4};"
                 :: "l"(p), "f"(a), "f"(b), "f"(c), "f"(d) : "memory");
}

// ---------------------------------------------------------------------------
// Node kernel 1: h1 = x @ W1 (512x16), alpha terms, init z/acc.
// Block = 256 threads = 256 nodes. x staged through smem in 32-wide k tiles
// (coalesced), W tile (32x16) staged per iteration, read as float4 broadcast.
// ---------------------------------------------------------------------------
#define N1_THREADS 256
#define KTILE 32

__global__ void __launch_bounds__(N1_THREADS)
node1_kernel(const float* __restrict__ x, const float* __restrict__ W1,
             const float* __restrict__ a_s, const float* __restrict__ a_d, int n)
{
    __shared__ float  xs[N1_THREADS][KTILE + 1];   // +1 pad: conflict-free xs[t][kk]
    __shared__ float4 Wt4[KTILE * 4];              // 32 x 16 W slice
    __shared__ float  avs[HID], avd[HID];

    const int t = threadIdx.x;
    const int node0 = blockIdx.x * N1_THREADS;
    const int node = node0 + t;

    if (t < HID)       avs[t] = a_s[t];
    else if (t < 2*HID) avd[t - HID] = a_d[t - HID];

    float acc[HID];
#pragma unroll
    for (int c = 0; c < HID; c++) acc[c] = 0.f;

    for (int kb = 0; kb < IN_DIM; kb += KTILE) {
        __syncthreads();
        // stage W slice: KTILE*16 = 512 floats, rows contiguous in global
        {
            float* Wtf = (float*)Wt4;
#pragma unroll
            for (int j = t; j < KTILE * HID; j += N1_THREADS)
                Wtf[j] = W1[kb * HID + j];
        }
        // stage x tile: 256 nodes x 32 k, coalesced
#pragma unroll
        for (int i = 0; i < KTILE; i++) {
            int j = t + N1_THREADS * i;      // 0..8191
            int row = j >> 5;
            int col = j & 31;
            int nr = node0 + row;
            xs[row][col] = (nr < n) ? x[(size_t)nr * IN_DIM + kb + col] : 0.f;
        }
        __syncthreads();

        if (node < n) {
#pragma unroll
            for (int kk = 0; kk < KTILE; kk++) {
                float xv = xs[t][kk];
                float4 w0 = Wt4[kk * 4 + 0];
                float4 w1 = Wt4[kk * 4 + 1];
                float4 w2 = Wt4[kk * 4 + 2];
                float4 w3 = Wt4[kk * 4 + 3];
                acc[0]  = fmaf(xv, w0.x, acc[0]);
                acc[1]  = fmaf(xv, w0.y, acc[1]);
                acc[2]  = fmaf(xv, w0.z, acc[2]);
                acc[3]  = fmaf(xv, w0.w, acc[3]);
                acc[4]  = fmaf(xv, w1.x, acc[4]);
                acc[5]  = fmaf(xv, w1.y, acc[5]);
                acc[6]  = fmaf(xv, w1.z, acc[6]);
                acc[7]  = fmaf(xv, w1.w, acc[7]);
                acc[8]  = fmaf(xv, w2.x, acc[8]);
                acc[9]  = fmaf(xv, w2.y, acc[9]);
                acc[10] = fmaf(xv, w2.z, acc[10]);
                acc[11] = fmaf(xv, w2.w, acc[11]);
                acc[12] = fmaf(xv, w3.x, acc[12]);
                acc[13] = fmaf(xv, w3.y, acc[13]);
                acc[14] = fmaf(xv, w3.z, acc[14]);
                acc[15] = fmaf(xv, w3.w, acc[15]);
            }
        }
    }
    if (node >= n) return;

    float as_v = 0.f, ad_v = 0.f;
#pragma unroll
    for (int c = 0; c < HID; c++) {
        as_v = fmaf(acc[c], avs[c], as_v);
        ad_v = fmaf(acc[c], avd[c], ad_v);
    }

    float4* hp = (float4*)(g_h + (size_t)node * HID);
    hp[0] = make_float4(acc[0],  acc[1],  acc[2],  acc[3]);
    hp[1] = make_float4(acc[4],  acc[5],  acc[6],  acc[7]);
    hp[2] = make_float4(acc[8],  acc[9],  acc[10], acc[11]);
    hp[3] = make_float4(acc[12], acc[13], acc[14], acc[15]);

    g_as[node] = as_v;
    g_ad[node] = ad_v;
    g_z[node]  = 0.f;
    float4 zero4 = make_float4(0.f, 0.f, 0.f, 0.f);
    float4* ap = (float4*)(g_acc + (size_t)node * HID);
    ap[0] = zero4; ap[1] = zero4; ap[2] = zero4; ap[3] = zero4;
}

// ---------------------------------------------------------------------------
// Fused edge kernel: softmax numerator sum + weighted aggregation.
// i < E: real edge (src=ei[i], dst=ei[E+i]); i >= E: self loop (i-E).
// ---------------------------------------------------------------------------
__global__ void __launch_bounds__(256)
edge_kernel(const int* __restrict__ ei, int E, int n)
{
    int i = blockIdx.x * blockDim.x + threadIdx.x;
    int total = E + n;
    if (i >= total) return;

    int s, d;
    if (i < E) { s = ei[i]; d = ei[E + i]; }
    else       { s = i - E; d = s; }

    float v = g_as[s] + g_ad[d];
    v = (v > 0.f) ? v : 0.2f * v;           // leaky relu, slope 0.2
    float e = __expf(v);                    // max-shift skipped (logits O(1))

    atomicAdd(&g_z[d], e);

    const float4* hp = (const float4*)(g_h + (size_t)s * HID);
    float4 h0 = hp[0], h1 = hp[1], h2 = hp[2], h3 = hp[3];

    float* ap = g_acc + (size_t)d * HID;
    redAdd4(ap + 0,  e * h0.x, e * h0.y, e * h0.z, e * h0.w);
    redAdd4(ap + 4,  e * h1.x, e * h1.y, e * h1.z, e * h1.w);
    redAdd4(ap + 8,  e * h2.x, e * h2.y, e * h2.z, e * h2.w);
    redAdd4(ap + 12, e * h3.x, e * h3.y, e * h3.z, e * h3.w);
}

// ---------------------------------------------------------------------------
// Node kernel 2: finish layer-1 softmax-agg, relu, h2 = hin@W2, new alphas,
// reset z/acc for layer 2.
// ---------------------------------------------------------------------------
__global__ void __launch_bounds__(256)
node_mid_kernel(const float* __restrict__ W2, const float* __restrict__ a_s,
                const float* __restrict__ a_d, const float* __restrict__ b,
                int n)
{
    __shared__ float Ws[HID * HID];
    __shared__ float avs[HID], avd[HID], bs[HID];
    const int t = threadIdx.x;
    if (t < HID * HID) Ws[t] = W2[t];
    if (t < HID) { avs[t] = a_s[t]; avd[t] = a_d[t]; bs[t] = b[t]; }
    __syncthreads();

    int i = blockIdx.x * blockDim.x + t;
    if (i >= n) return;

    float inv = 1.f / (g_z[i] + 1e-16f);
    const float4* ap = (const float4*)(g_acc + (size_t)i * HID);
    float4 a0 = ap[0], a1 = ap[1], a2 = ap[2], a3 = ap[3];
    float hin[HID];
    hin[0]  = a0.x; hin[1]  = a0.y; hin[2]  = a0.z; hin[3]  = a0.w;
    hin[4]  = a1.x; hin[5]  = a1.y; hin[6]  = a1.z; hin[7]  = a1.w;
    hin[8]  = a2.x; hin[9]  = a2.y; hin[10] = a2.z; hin[11] = a2.w;
    hin[12] = a3.x; hin[13] = a3.y; hin[14] = a3.z; hin[15] = a3.w;
#pragma unroll
    for (int c = 0; c < HID; c++)
        hin[c] = fmaxf(fmaf(hin[c], inv, bs[c]), 0.f);

    float h2[HID];
#pragma unroll
    for (int j = 0; j < HID; j++) h2[j] = 0.f;
#pragma unroll
    for (int c = 0; c < HID; c++) {
        float v = hin[c];
#pragma unroll
        for (int j = 0; j < HID; j++)
            h2[j] = fmaf(v, Ws[c * HID + j], h2[j]);
    }

    float as_v = 0.f, ad_v = 0.f;
#pragma unroll
    for (int c = 0; c < HID; c++) {
        as_v = fmaf(h2[c], avs[c], as_v);
        ad_v = fmaf(h2[c], avd[c], ad_v);
    }

    float4* hp = (float4*)(g_h + (size_t)i * HID);
    hp[0] = make_float4(h2[0],  h2[1],  h2[2],  h2[3]);
    hp[1] = make_float4(h2[4],  h2[5],  h2[6],  h2[7]);
    hp[2] = make_float4(h2[8],  h2[9],  h2[10], h2[11]);
    hp[3] = make_float4(h2[12], h2[13], h2[14], h2[15]);

    g_as[i] = as_v;
    g_ad[i] = ad_v;
    g_z[i]  = 0.f;
    float4 zero4 = make_float4(0.f, 0.f, 0.f, 0.f);
    float4* cp = (float4*)(g_acc + (size_t)i * HID);
    cp[0] = zero4; cp[1] = zero4; cp[2] = zero4; cp[3] = zero4;
}

// ---------------------------------------------------------------------------
// Node kernel 3: finish layer-2, relu, logits = h@Wout + bout, softmax, write.
// ---------------------------------------------------------------------------
__global__ void __launch_bounds__(256)
node_out_kernel(const float* __restrict__ Wout, const float* __restrict__ bout,
                const float* __restrict__ b, float* __restrict__ out, int n)
{
    __shared__ float Ws[HID * HID];
    __shared__ float bos[HID], bs[HID];
    const int t = threadIdx.x;
    if (t < HID * HID) Ws[t] = Wout[t];
    if (t < HID) { bos[t] = bout[t]; bs[t] = b[t]; }
    __syncthreads();

    int i = blockIdx.x * blockDim.x + t;
    if (i >= n) return;

    float inv = 1.f / (g_z[i] + 1e-16f);
    const float4* ap = (const float4*)(g_acc + (size_t)i * HID);
    float4 a0 = ap[0], a1 = ap[1], a2 = ap[2], a3 = ap[3];
    float hin[HID];
    hin[0]  = a0.x; hin[1]  = a0.y; hin[2]  = a0.z; hin[3]  = a0.w;
    hin[4]  = a1.x; hin[5]  = a1.y; hin[6]  = a1.z; hin[7]  = a1.w;
    hin[8]  = a2.x; hin[9]  = a2.y; hin[10] = a2.z; hin[11] = a2.w;
    hin[12] = a3.x; hin[13] = a3.y; hin[14] = a3.z; hin[15] = a3.w;
#pragma unroll
    for (int c = 0; c < HID; c++)
        hin[c] = fmaxf(fmaf(hin[c], inv, bs[c]), 0.f);

    float l[HID];
#pragma unroll
    for (int j = 0; j < HID; j++) l[j] = bos[j];
#pragma unroll
    for (int c = 0; c < HID; c++) {
        float v = hin[c];
#pragma unroll
        for (int j = 0; j < HID; j++)
            l[j] = fmaf(v, Ws[c * HID + j], l[j]);
    }

    float m = l[0];
#pragma unroll
    for (int j = 1; j < HID; j++) m = fmaxf(m, l[j]);
    float ssum = 0.f;
#pragma unroll
    for (int j = 0; j < HID; j++) { l[j] = __expf(l[j] - m); ssum += l[j]; }
    float sinv = 1.f / ssum;

    float4* op = (float4*)(out + (size_t)i * HID);
    op[0] = make_float4(l[0]  * sinv, l[1]  * sinv, l[2]  * sinv, l[3]  * sinv);
    op[1] = make_float4(l[4]  * sinv, l[5]  * sinv, l[6]  * sinv, l[7]  * sinv);
    op[2] = make_float4(l[8]  * sinv, l[9]  * sinv, l[10] * sinv, l[11] * sinv);
    op[3] = make_float4(l[12] * sinv, l[13] * sinv, l[14] * sinv, l[15] * sinv);
}

// ---------------------------------------------------------------------------
extern "C" void kernel_launch(void* const* d_in, const int* in_sizes, int n_in,
                              void* d_out, int out_size)
{
    const float* x    = (const float*)d_in[0];
    const float* W1   = (const float*)d_in[1];
    const float* as1  = (const float*)d_in[2];
    const float* ad1  = (const float*)d_in[3];
    const float* b1   = (const float*)d_in[4];
    const float* W2   = (const float*)d_in[5];
    const float* as2  = (const float*)d_in[6];
    const float* ad2  = (const float*)d_in[7];
    const float* b2   = (const float*)d_in[8];
    const float* Wout = (const float*)d_in[9];
    const float* bout = (const float*)d_in[10];
    const int*   ei   = (const int*)d_in[11];

    int n = in_sizes[0] / IN_DIM;
    int E = in_sizes[11] / 2;
    float* out = (float*)d_out;

    int nodeBlocks = (n + 255) / 256;
    int total = E + n;
    int edgeBlocks = (total + 255) / 256;

    node1_kernel<<<nodeBlocks, N1_THREADS>>>(x, W1, as1, ad1, n);
    edge_kernel<<<edgeBlocks, 256>>>(ei, E, n);
    node_mid_kernel<<<nodeBlocks, 256>>>(W2, as2, ad2, b1, n);
    edge_kernel<<<edgeBlocks, 256>>>(ei, E, n);
    node_out_kernel<<<nodeBlocks, 256>>>(Wout, bout, b2, out, n);
}

// round 3
// speedup vs baseline: 1.1360x; 1.1360x over previous
#include <cuda_runtime.h>
#include <cuda_bf16.h>

// ---------------------------------------------------------------------------
// GAT 2-layer + softmax head, CSR-based (atomic-free) edge aggregation.
//
//   layer: h = x@W ; as = h@a_src ; ad = h@a_dst
//          per dst d: z = sum_e exp(lrelu(as[s]+ad[d])), acc = sum_e e*h[s]
//          (edges = incoming CSR edges + implicit self loop)
//          next input = relu(acc/z + b)
//   Max-shift skipped (softmax shift-invariant, logits O(1)); division by z
//   deferred to the following node kernel.
//
// CSR (src sorted by dst) is rebuilt inside the graph every replay:
//   zero -> histogram -> scan(A/B/C) -> scatter.  Aggregation is gather-only.
// ---------------------------------------------------------------------------

#define NMAX   100000
#define EMAX   3400000
#define IN_DIM 512
#define HID    16

// persistent scratch (no allocation allowed)
__device__ __align__(16) float g_h[NMAX * HID];
__device__ __align__(16) float g_acc[NMAX * HID];
__device__ float g_as[NMAX];
__device__ float g_ad[NMAX];
__device__ float g_z[NMAX];

__device__ int g_deg[NMAX];
__device__ int g_off[NMAX + 1];
__device__ int g_cur[NMAX];
__device__ int g_csr[EMAX];
__device__ int g_bsum[128];
__device__ int g_bpre[128];

// ---------------------------------------------------------------------------
// Node kernel 1: h1 = x @ W1 (512x16), alpha terms.
// Whole W1 in smem (32KB); each thread streams its own x row (LDG.128 pairs).
// ---------------------------------------------------------------------------
__global__ void __launch_bounds__(256)
node1_kernel(const float* __restrict__ x, const float* __restrict__ W1,
             const float* __restrict__ a_s, const float* __restrict__ a_d, int n)
{
    __shared__ float Ws[IN_DIM * HID];   // 32 KB
    __shared__ float avs[HID], avd[HID];

    const int t = threadIdx.x;
    for (int j = t; j < IN_DIM * HID / 4; j += 256)
        ((float4*)Ws)[j] = ((const float4*)W1)[j];
    if (t < HID)            avs[t] = a_s[t];
    else if (t < 2 * HID)   avd[t - HID] = a_d[t - HID];
    __syncthreads();

    const int node = blockIdx.x * 256 + t;
    if (node >= n) return;

    const float4* xp = (const float4*)(x + (size_t)node * IN_DIM);

    float acc[HID];
#pragma unroll
    for (int c = 0; c < HID; c++) acc[c] = 0.f;

#pragma unroll 4
    for (int kb = 0; kb < IN_DIM / 8; kb++) {
        float4 xa = xp[kb * 2];
        float4 xb = xp[kb * 2 + 1];
        float xv[8] = {xa.x, xa.y, xa.z, xa.w, xb.x, xb.y, xb.z, xb.w};
#pragma unroll
        for (int kk = 0; kk < 8; kk++) {
            const float4* wr = (const float4*)(Ws + (kb * 8 + kk) * HID);
            float4 w0 = wr[0], w1 = wr[1], w2 = wr[2], w3 = wr[3];
            float v = xv[kk];
            acc[0]  = fmaf(v, w0.x, acc[0]);
            acc[1]  = fmaf(v, w0.y, acc[1]);
            acc[2]  = fmaf(v, w0.z, acc[2]);
            acc[3]  = fmaf(v, w0.w, acc[3]);
            acc[4]  = fmaf(v, w1.x, acc[4]);
            acc[5]  = fmaf(v, w1.y, acc[5]);
            acc[6]  = fmaf(v, w1.z, acc[6]);
            acc[7]  = fmaf(v, w1.w, acc[7]);
            acc[8]  = fmaf(v, w2.x, acc[8]);
            acc[9]  = fmaf(v, w2.y, acc[9]);
            acc[10] = fmaf(v, w2.z, acc[10]);
            acc[11] = fmaf(v, w2.w, acc[11]);
            acc[12] = fmaf(v, w3.x, acc[12]);
            acc[13] = fmaf(v, w3.y, acc[13]);
            acc[14] = fmaf(v, w3.z, acc[14]);
            acc[15] = fmaf(v, w3.w, acc[15]);
        }
    }

    float as_v = 0.f, ad_v = 0.f;
#pragma unroll
    for (int c = 0; c < HID; c++) {
        as_v = fmaf(acc[c], avs[c], as_v);
        ad_v = fmaf(acc[c], avd[c], ad_v);
    }

    float4* hp = (float4*)(g_h + (size_t)node * HID);
    hp[0] = make_float4(acc[0],  acc[1],  acc[2],  acc[3]);
    hp[1] = make_float4(acc[4],  acc[5],  acc[6],  acc[7]);
    hp[2] = make_float4(acc[8],  acc[9],  acc[10], acc[11]);
    hp[3] = make_float4(acc[12], acc[13], acc[14], acc[15]);
    g_as[node] = as_v;
    g_ad[node] = ad_v;
}

// ---------------------------------------------------------------------------
// CSR construction kernels
// ---------------------------------------------------------------------------
__global__ void zero_deg_kernel(int n)
{
    int i = blockIdx.x * blockDim.x + threadIdx.x;
    if (i < n) g_deg[i] = 0;
}

__global__ void hist_kernel(const int* __restrict__ ei, int E)
{
    int i = blockIdx.x * blockDim.x + threadIdx.x;
    if (i < E) atomicAdd(&g_deg[ei[E + i]], 1);
}

// block-wise exclusive scan of deg -> off (partial), block totals -> bsum
__global__ void __launch_bounds__(1024)
scanA_kernel(int n)
{
    __shared__ int sm[1024];
    int t = threadIdx.x;
    int i = blockIdx.x * 1024 + t;
    int v = (i < n) ? g_deg[i] : 0;
    sm[t] = v;
    __syncthreads();
#pragma unroll
    for (int ofs = 1; ofs < 1024; ofs <<= 1) {
        int add = (t >= ofs) ? sm[t - ofs] : 0;
        __syncthreads();
        sm[t] += add;
        __syncthreads();
    }
    if (i < n) g_off[i] = sm[t] - v;          // exclusive within block
    if (t == 1023) g_bsum[blockIdx.x] = sm[t];
}

// scan of block sums (nb <= 128)
__global__ void __launch_bounds__(128)
scanB_kernel(int nb, int n)
{
    __shared__ int sm[128];
    int t = threadIdx.x;
    int v = (t < nb) ? g_bsum[t] : 0;
    sm[t] = v;
    __syncthreads();
#pragma unroll
    for (int ofs = 1; ofs < 128; ofs <<= 1) {
        int add = (t >= ofs) ? sm[t - ofs] : 0;
        __syncthreads();
        sm[t] += add;
        __syncthreads();
    }
    if (t < nb) g_bpre[t] = sm[t] - v;        // exclusive
    if (t == 127) g_off[n] = sm[127];         // total (= E)
}

__global__ void __launch_bounds__(1024)
scanC_kernel(int n)
{
    int i = blockIdx.x * 1024 + threadIdx.x;
    if (i < n) {
        int o = g_off[i] + g_bpre[blockIdx.x];
        g_off[i] = o;
        g_cur[i] = o;
    }
}

__global__ void scatter_kernel(const int* __restrict__ ei, int E)
{
    int i = blockIdx.x * blockDim.x + threadIdx.x;
    if (i < E) {
        int d = ei[E + i];
        int pos = atomicAdd(&g_cur[d], 1);
        g_csr[pos] = ei[i];
    }
}

// ---------------------------------------------------------------------------
// Atomic-free edge aggregation: one warp per dst node.
// Lanes = 2 edges x 16 features. Self loop handled inline (eidx == deg).
// Writes g_acc[d][0..15] and g_z[d] with plain stores.
// ---------------------------------------------------------------------------
#define AGG_WARPS 8

__global__ void __launch_bounds__(AGG_WARPS * 32)
agg_kernel(int n)
{
    int d = blockIdx.x * AGG_WARPS + (threadIdx.x >> 5);
    if (d >= n) return;
    int lane = threadIdx.x & 31;
    int c    = lane & 15;
    int half = lane >> 4;

    int begin = g_off[d];
    int deg   = g_off[d + 1] - begin;
    int nE    = deg + 1;                       // + self loop
    float ad_d = g_ad[d];

    float zacc = 0.f;
    float facc = 0.f;

    // full 32-edge batches
    int fullB = nE >> 5;
    for (int b = 0; b < fullB; b++) {
        int eidx = (b << 5) + lane;
        int s = (eidx < deg) ? g_csr[begin + eidx] : d;
        float v = g_as[s] + ad_d;
        v = (v > 0.f) ? v : 0.2f * v;
        float e = __expf(v);
        zacc += e;
#pragma unroll
        for (int j = 0; j < 16; j++) {
            int   sl = j * 2 + half;
            float e2 = __shfl_sync(0xffffffff, e, sl);
            int   s2 = __shfl_sync(0xffffffff, s, sl);
            facc = fmaf(e2, g_h[s2 * HID + c], facc);
        }
    }
    // tail batch
    int b0 = fullB << 5;
    if (b0 < nE) {
        int eidx = b0 + lane;
        bool valid = eidx < nE;
        int s = (eidx < deg) ? g_csr[begin + eidx] : d;
        float v = g_as[s] + ad_d;
        v = (v > 0.f) ? v : 0.2f * v;
        float e = valid ? __expf(v) : 0.f;
        zacc += e;
        int m = nE - b0;
        int iters = (m + 1) >> 1;
#pragma unroll 4
        for (int j = 0; j < iters; j++) {
            int   sl = j * 2 + half;           // may index an e==0 lane: safe
            float e2 = __shfl_sync(0xffffffff, e, sl);
            int   s2 = __shfl_sync(0xffffffff, s, sl);
            facc = fmaf(e2, g_h[s2 * HID + c], facc);
        }
    }

    // combine edge-halves for each feature
    facc += __shfl_xor_sync(0xffffffff, facc, 16);
    // z reduction
    zacc += __shfl_xor_sync(0xffffffff, zacc, 16);
    zacc += __shfl_xor_sync(0xffffffff, zacc, 8);
    zacc += __shfl_xor_sync(0xffffffff, zacc, 4);
    zacc += __shfl_xor_sync(0xffffffff, zacc, 2);
    zacc += __shfl_xor_sync(0xffffffff, zacc, 1);

    if (lane < 16) g_acc[d * HID + c] = facc;
    if (lane == 0) g_z[d] = zacc;
}

// ---------------------------------------------------------------------------
// Node kernel 2: finish layer-1 softmax-agg, relu, h2 = hin@W2, new alphas.
// ---------------------------------------------------------------------------
__global__ void __launch_bounds__(256)
node_mid_kernel(const float* __restrict__ W2, const float* __restrict__ a_s,
                const float* __restrict__ a_d, const float* __restrict__ b,
                int n)
{
    __shared__ float Ws[HID * HID];
    __shared__ float avs[HID], avd[HID], bs[HID];
    const int t = threadIdx.x;
    if (t < HID * HID) Ws[t] = W2[t];
    if (t < HID) { avs[t] = a_s[t]; avd[t] = a_d[t]; bs[t] = b[t]; }
    __syncthreads();

    int i = blockIdx.x * blockDim.x + t;
    if (i >= n) return;

    float inv = 1.f / (g_z[i] + 1e-16f);
    const float4* ap = (const float4*)(g_acc + (size_t)i * HID);
    float4 a0 = ap[0], a1 = ap[1], a2 = ap[2], a3 = ap[3];
    float hin[HID] = {a0.x, a0.y, a0.z, a0.w, a1.x, a1.y, a1.z, a1.w,
                      a2.x, a2.y, a2.z, a2.w, a3.x, a3.y, a3.z, a3.w};
#pragma unroll
    for (int c = 0; c < HID; c++)
        hin[c] = fmaxf(fmaf(hin[c], inv, bs[c]), 0.f);

    float h2[HID];
#pragma unroll
    for (int j = 0; j < HID; j++) h2[j] = 0.f;
#pragma unroll
    for (int c = 0; c < HID; c++) {
        float v = hin[c];
#pragma unroll
        for (int j = 0; j < HID; j++)
            h2[j] = fmaf(v, Ws[c * HID + j], h2[j]);
    }

    float as_v = 0.f, ad_v = 0.f;
#pragma unroll
    for (int c = 0; c < HID; c++) {
        as_v = fmaf(h2[c], avs[c], as_v);
        ad_v = fmaf(h2[c], avd[c], ad_v);
    }

    float4* hp = (float4*)(g_h + (size_t)i * HID);
    hp[0] = make_float4(h2[0],  h2[1],  h2[2],  h2[3]);
    hp[1] = make_float4(h2[4],  h2[5],  h2[6],  h2[7]);
    hp[2] = make_float4(h2[8],  h2[9],  h2[10], h2[11]);
    hp[3] = make_float4(h2[12], h2[13], h2[14], h2[15]);
    g_as[i] = as_v;
    g_ad[i] = ad_v;
}

// ---------------------------------------------------------------------------
// Node kernel 3: finish layer-2, relu, logits = h@Wout + bout, softmax, write.
// ---------------------------------------------------------------------------
__global__ void __launch_bounds__(256)
node_out_kernel(const float* __restrict__ Wout, const float* __restrict__ bout,
                const float* __restrict__ b, float* __restrict__ out, int n)
{
    __shared__ float Ws[HID * HID];
    __shared__ float bos[HID], bs[HID];
    const int t = threadIdx.x;
    if (t < HID * HID) Ws[t] = Wout[t];
    if (t < HID) { bos[t] = bout[t]; bs[t] = b[t]; }
    __syncthreads();

    int i = blockIdx.x * blockDim.x + t;
    if (i >= n) return;

    float inv = 1.f / (g_z[i] + 1e-16f);
    const float4* ap = (const float4*)(g_acc + (size_t)i * HID);
    float4 a0 = ap[0], a1 = ap[1], a2 = ap[2], a3 = ap[3];
    float hin[HID] = {a0.x, a0.y, a0.z, a0.w, a1.x, a1.y, a1.z, a1.w,
                      a2.x, a2.y, a2.z, a2.w, a3.x, a3.y, a3.z, a3.w};
#pragma unroll
    for (int c = 0; c < HID; c++)
        hin[c] = fmaxf(fmaf(hin[c], inv, bs[c]), 0.f);

    float l[HID];
#pragma unroll
    for (int j = 0; j < HID; j++) l[j] = bos[j];
#pragma unroll
    for (int c = 0; c < HID; c++) {
        float v = hin[c];
#pragma unroll
        for (int j = 0; j < HID; j++)
            l[j] = fmaf(v, Ws[c * HID + j], l[j]);
    }

    float m = l[0];
#pragma unroll
    for (int j = 1; j < HID; j++) m = fmaxf(m, l[j]);
    float ssum = 0.f;
#pragma unroll
    for (int j = 0; j < HID; j++) { l[j] = __expf(l[j] - m); ssum += l[j]; }
    float sinv = 1.f / ssum;

    float4* op = (float4*)(out + (size_t)i * HID);
    op[0] = make_float4(l[0]  * sinv, l[1]  * sinv, l[2]  * sinv, l[3]  * sinv);
    op[1] = make_float4(l[4]  * sinv, l[5]  * sinv, l[6]  * sinv, l[7]  * sinv);
    op[2] = make_float4(l[8]  * sinv, l[9]  * sinv, l[10] * sinv, l[11] * sinv);
    op[3] = make_float4(l[12] * sinv, l[13] * sinv, l[14] * sinv, l[15] * sinv);
}

// ---------------------------------------------------------------------------
extern "C" void kernel_launch(void* const* d_in, const int* in_sizes, int n_in,
                              void* d_out, int out_size)
{
    const float* x    = (const float*)d_in[0];
    const float* W1   = (const float*)d_in[1];
    const float* as1  = (const float*)d_in[2];
    const float* ad1  = (const float*)d_in[3];
    const float* b1   = (const float*)d_in[4];
    const float* W2   = (const float*)d_in[5];
    const float* as2  = (const float*)d_in[6];
    const float* ad2  = (const float*)d_in[7];
    const float* b2   = (const float*)d_in[8];
    const float* Wout = (const float*)d_in[9];
    const float* bout = (const float*)d_in[10];
    const int*   ei   = (const int*)d_in[11];

    int n = in_sizes[0] / IN_DIM;
    int E = in_sizes[11] / 2;
    float* out = (float*)d_out;

    int nodeBlocks = (n + 255) / 256;
    int edgeBlocks = (E + 255) / 256;
    int scanBlocks = (n + 1023) / 1024;
    int aggBlocks  = (n + AGG_WARPS - 1) / AGG_WARPS;

    // CSR build + layer-1 node transform
    zero_deg_kernel<<<nodeBlocks, 256>>>(n);
    node1_kernel<<<nodeBlocks, 256>>>(x, W1, as1, ad1, n);
    hist_kernel<<<edgeBlocks, 256>>>(ei, E);
    scanA_kernel<<<scanBlocks, 1024>>>(n);
    scanB_kernel<<<1, 128>>>(scanBlocks, n);
    scanC_kernel<<<scanBlocks, 1024>>>(n);
    scatter_kernel<<<edgeBlocks, 256>>>(ei, E);

    // layer 1 aggregation + layer 2
    agg_kernel<<<aggBlocks, AGG_WARPS * 32>>>(n);
    node_mid_kernel<<<nodeBlocks, 256>>>(W2, as2, ad2, b1, n);
    agg_kernel<<<aggBlocks, AGG_WARPS * 32>>>(n);
    node_out_kernel<<<nodeBlocks, 256>>>(Wout, bout, b2, out, n);
}